// round 10
// baseline (speedup 1.0000x reference)
#include <cuda_runtime.h>
#include <cstdint>
#include <math.h>

#define B_   64
#define S_   1024
#define I_   256
#define H_   512
#define O_   512
#define G3H  1536

#define GR    96     // 3 groups x 32 CTAs, all resident (1 CTA/SM via smem)
#define RT    512    // 16 warps -> 4 per SMSP (latency hiding)
#define STEPS 1026

typedef unsigned long long u64;

// ---------------------------------------------------------------------------
// Device-global scratch
// ---------------------------------------------------------------------------
__device__ float    g_gi0  [(size_t)S_ * G3H * B_];   // gi0 [t][row][b]
__device__ float    g_gi1  [2 * G3H * B_];            // gi1 ring [slot][row][b]
__device__ float    g_h1sq [(size_t)S_ * H_ * B_];    // hseq1 transposed [t][j][b]
__device__ float    g_h0T  [2 * H_ * B_];             // h0 double buffer [slot][j][b]
__device__ float    g_h1T  [2 * H_ * B_];             // h1 double buffer [slot][j][b]
__device__ unsigned g_sync [32];                      // [0] = barrier counter

// ---------------------------------------------------------------------------
// f32x2 + cp.async helpers
// ---------------------------------------------------------------------------
__device__ __forceinline__ u64 pk2(float x) {
    u64 r; asm("mov.b64 %0, {%1, %1};" : "=l"(r) : "r"(__float_as_uint(x))); return r;
}
__device__ __forceinline__ void fma2(u64& d, u64 a, u64 b) {
    asm("fma.rn.f32x2 %0, %1, %2, %0;" : "+l"(d) : "l"(a), "l"(b));
}
__device__ __forceinline__ void add2(u64& d, u64 a) {
    asm("add.rn.f32x2 %0, %0, %1;" : "+l"(d) : "l"(a));
}
__device__ __forceinline__ float2 up2(u64 u) {
    unsigned lo, hi; asm("mov.b64 {%0, %1}, %2;" : "=r"(lo), "=r"(hi) : "l"(u));
    return make_float2(__uint_as_float(lo), __uint_as_float(hi));
}
__device__ __forceinline__ void cpa16(float* smem, const float* g) {
    unsigned s = (unsigned)__cvta_generic_to_shared(smem);
    asm volatile("cp.async.cg.shared.global [%0], [%1], 16;" :: "r"(s), "l"(g));
}
__device__ __forceinline__ float sigmoidf_(float x) { return 1.f / (1.f + expf(-x)); }

// ---------------------------------------------------------------------------
// SGEMM + bias. MODE 0: gi layout. MODE 3: logits layout.
// ---------------------------------------------------------------------------
template <int MODE>
__global__ void __launch_bounds__(256)
sgemm_bias(const float* __restrict__ A, const float* __restrict__ Bw,
           const float* __restrict__ bias, float* __restrict__ out,
           int M, int N, int K)
{
    __shared__ float As[16][132];
    __shared__ float Bs[16][68];

    const int tid = threadIdx.x;
    const int m0  = blockIdx.y * 128;
    const int n0  = blockIdx.x * 64;
    const int tx  = tid & 15;
    const int ty  = tid >> 4;

    const float* Bb = Bw + (size_t)n0 * K;

    u64 acc[4][4];
#pragma unroll
    for (int i = 0; i < 4; i++)
#pragma unroll
        for (int j = 0; j < 4; j++) acc[i][j] = 0ull;

    const int lr = tid >> 2;
    const int lk = (tid & 3) * 4;
    const int t0 = m0 >> 6;
    const int kk = tid >> 4, qq = tid & 15;

    for (int kt = 0; kt < K; kt += 16) {
        if (MODE == 0) {
            const float* Ab = A + (size_t)m0 * K;
#pragma unroll
            for (int p = 0; p < 2; p++) {
                float4 v = *(const float4*)&Ab[(size_t)(lr + p * 64) * K + kt + lk];
                As[lk + 0][lr + p * 64] = v.x;
                As[lk + 1][lr + p * 64] = v.y;
                As[lk + 2][lr + p * 64] = v.z;
                As[lk + 3][lr + p * 64] = v.w;
            }
        } else {
            float4 v0 = *(const float4*)&A[(((size_t)t0       * 512) + kt + kk) * 64 + qq * 4];
            float4 v1 = *(const float4*)&A[(((size_t)(t0 + 1) * 512) + kt + kk) * 64 + qq * 4];
            *(float4*)&As[kk][qq * 4]      = v0;
            *(float4*)&As[kk][64 + qq * 4] = v1;
        }
        {
            float4 v = *(const float4*)&Bb[(size_t)lr * K + kt + lk];
            Bs[lk + 0][lr] = v.x;
            Bs[lk + 1][lr] = v.y;
            Bs[lk + 2][lr] = v.z;
            Bs[lk + 3][lr] = v.w;
        }
        __syncthreads();

#pragma unroll
        for (int k = 0; k < 16; k++) {
            float4 bv = *(const float4*)&Bs[k][tx * 4];
            u64 bp0 = pk2(bv.x), bp1 = pk2(bv.y), bp2 = pk2(bv.z), bp3 = pk2(bv.w);
            ulonglong2 a01 = *(const ulonglong2*)&As[k][ty * 8];
            ulonglong2 a23 = *(const ulonglong2*)&As[k][ty * 8 + 4];
            u64 ap[4] = {a01.x, a01.y, a23.x, a23.y};
#pragma unroll
            for (int i = 0; i < 4; i++) {
                fma2(acc[i][0], ap[i], bp0);
                fma2(acc[i][1], ap[i], bp1);
                fma2(acc[i][2], ap[i], bp2);
                fma2(acc[i][3], ap[i], bp3);
            }
        }
        __syncthreads();
    }

    float accf[8][4];
#pragma unroll
    for (int i = 0; i < 4; i++)
#pragma unroll
        for (int j = 0; j < 4; j++) {
            float2 v = up2(acc[i][j]);
            accf[2 * i + 0][j] = v.x;
            accf[2 * i + 1][j] = v.y;
        }

    float bv[4];
    *(float4*)bv = *(const float4*)&bias[n0 + tx * 4];

#pragma unroll
    for (int i = 0; i < 8; i++) {
        int m = m0 + ty * 8 + i;
        if (MODE == 3) {
            int t = m >> 6, b = m & 63;
            float4 c;
            c.x = accf[i][0] + bv[0];
            c.y = accf[i][1] + bv[1];
            c.z = accf[i][2] + bv[2];
            c.w = accf[i][3] + bv[3];
            *(float4*)&out[((size_t)b * S_ + t) * O_ + n0 + tx * 4] = c;
        } else {
            int t = m & (S_ - 1), b = m >> 10;
#pragma unroll
            for (int j = 0; j < 4; j++)
                out[((size_t)t * G3H + n0 + tx * 4 + j) * B_ + b] = accf[i][j] + bv[j];
        }
    }
}

// ---------------------------------------------------------------------------
// Fused two-layer GRU wavefront. 96 CTAs = 3 groups x 32 (16 j each), RT=512.
//  G0: h0[s] = cell(h0[s-1], gi0[s]);  G1: gi1[s-1] = h0[s-1]@W_ih1^T + b;
//  G2: h1[s-2] = cell(h1[s-3], gi1[s-2]).
// Weights pre-duplicated as f32x2 pairs in smem (192 KB); h streamed via
// 2 x 16 KB cp.async double buffer (8 chunks of 64 k).
// Thread = (kh, jl, bs): k-half x 16 j x 16 b-groups of 4.
// smem bytes: hbuf 32768 @0 | Wrz ulonglong2 131072 @32768 | Wn u64 65536 @163840
// ---------------------------------------------------------------------------
#define FUS_SMEM_BYTES 229376

template <int C>
__device__ __forceinline__ void chunk_compute(const float* __restrict__ hb,
                                              const ulonglong2* __restrict__ Wrz,
                                              const u64* __restrict__ Wn,
                                              int kh, int jl, int bA,
                                              u64* aR, u64* aZ, u64* aN)
{
    asm volatile("cp.async.wait_group %0;" :: "n"(C == 7 ? 0 : 1));
    __syncthreads();
    const float* hbuf = hb + (C & 1) * 4096;
#pragma unroll 8
    for (int i = 0; i < 32; i++) {
        const int kl = kh + 2 * i;
        const int kg = C * 64 + kl;
        ulonglong2 w2 = Wrz[kg * 16 + jl];
        u64 wn        = Wn [kg * 16 + jl];
        ulonglong2 h  = *(const ulonglong2*)&hbuf[kl * 64 + bA];
        fma2(aR[0], h.x, w2.x); fma2(aR[1], h.y, w2.x);
        fma2(aZ[0], h.x, w2.y); fma2(aZ[1], h.y, w2.y);
        fma2(aN[0], h.x, wn);   fma2(aN[1], h.y, wn);
    }
}

__device__ __forceinline__ void chunk_issue(float* hb, const float* hsrc,
                                            int c, int tid)
{
    const float* s4 = hsrc + c * 4096;
    float*       d4 = hb + (c & 1) * 4096;
#pragma unroll
    for (int u = 0; u < 2; u++)
        cpa16(d4 + (tid + u * RT) * 4, s4 + (tid + u * RT) * 4);
    asm volatile("cp.async.commit_group;");
}

__global__ void __launch_bounds__(RT, 1)
gru_fused(const float* __restrict__ gi0,
          const float* __restrict__ Whh0, const float* __restrict__ bhh0,
          const float* __restrict__ Wih1, const float* __restrict__ bih1,
          const float* __restrict__ Whh1, const float* __restrict__ bhh1,
          float* __restrict__ hid)    // [2][B][H] tail of d_out
{
    extern __shared__ float sm[];
    float*      hb  = sm;                                   // 32768 B
    ulonglong2* Wrz = (ulonglong2*)((char*)sm + 32768);     // 131072 B
    u64*        Wn  = (u64*)((char*)sm + 163840);           // 65536 B

    const int tid   = threadIdx.x;
    const int cta   = blockIdx.x;
    const int grp   = cta >> 5;
    const int lc    = cta & 31;
    const int jbase = lc * 16;

    const float* Wsrc = (grp == 0) ? Whh0 : (grp == 1) ? Wih1 : Whh1;

    // Pre-duplicated weight preload: 16 j x 512 k x 3 gates as packed f32x2.
    for (int i = tid; i < 16 * 512; i += RT) {
        int k = i & 511, jj = i >> 9;
        int j = jbase + jj;
        float wr = Wsrc[(size_t)j          * 512 + k];
        float wz = Wsrc[(size_t)(512 + j)  * 512 + k];
        float wn = Wsrc[(size_t)(1024 + j) * 512 + k];
        ulonglong2 wp; wp.x = pk2(wr); wp.y = pk2(wz);
        Wrz[k * 16 + jj] = wp;
        Wn [k * 16 + jj] = pk2(wn);
    }

    const int kh = tid >> 8;           // k-half: even/odd k
    const int rm = tid & 255;
    const int jl = rm >> 4;            // 0..15
    const int bs = rm & 15;            // 0..15
    const int bA = bs * 4;             // 4 batch per thread
    const int j  = jbase + jl;

    float br = 0.f, bz = 0.f, bn = 0.f;
    if (grp == 0) { br = bhh0[j]; bz = bhh0[512 + j]; bn = bhh0[1024 + j]; }
    if (grp == 1) { br = bih1[j]; bz = bih1[512 + j]; bn = bih1[1024 + j]; }
    if (grp == 2) { br = bhh1[j]; bz = bhh1[512 + j]; bn = bhh1[1024 + j]; }

    __syncthreads();

    for (int s = 0; s < STEPS; s++) {
        const bool active = (grp == 0) ? (s < 1024)
                          : (grp == 1) ? (s >= 1 && s < 1025)
                                       : (s >= 2);
        if (active) {
            const float* hsrc = ((grp == 2) ? g_h1T : g_h0T)
                              + (((grp == 2 ? s - 2 : s) + 1) & 1) * (H_ * B_);

            chunk_issue(hb, hsrc, 0, tid);
            chunk_issue(hb, hsrc, 1, tid);

            // Prefetch gi + h_old straight from global (arrives under mainloop)
            float GIR[4], GIZ[4], GIN[4], hold[4];
            if (kh == 0 && grp != 1) {
                const float* p = (grp == 0)
                    ? gi0   + (size_t)s * (G3H * 64)
                    : g_gi1 + (size_t)(s & 1) * (G3H * 64);
                *(float4*)&GIR[0]  = *(const float4*)&p[(size_t)j          * 64 + bA];
                *(float4*)&GIZ[0]  = *(const float4*)&p[(size_t)(512 + j)  * 64 + bA];
                *(float4*)&GIN[0]  = *(const float4*)&p[(size_t)(1024 + j) * 64 + bA];
                *(float4*)&hold[0] = *(const float4*)&hsrc[j * 64 + bA];
            }

            u64 aR[2] = {0,0}, aZ[2] = {0,0}, aN[2] = {0,0};

            chunk_compute<0>(hb, Wrz, Wn, kh, jl, bA, aR, aZ, aN);
            __syncthreads(); chunk_issue(hb, hsrc, 2, tid);
            chunk_compute<1>(hb, Wrz, Wn, kh, jl, bA, aR, aZ, aN);
            __syncthreads(); chunk_issue(hb, hsrc, 3, tid);
            chunk_compute<2>(hb, Wrz, Wn, kh, jl, bA, aR, aZ, aN);
            __syncthreads(); chunk_issue(hb, hsrc, 4, tid);
            chunk_compute<3>(hb, Wrz, Wn, kh, jl, bA, aR, aZ, aN);
            __syncthreads(); chunk_issue(hb, hsrc, 5, tid);
            chunk_compute<4>(hb, Wrz, Wn, kh, jl, bA, aR, aZ, aN);
            __syncthreads(); chunk_issue(hb, hsrc, 6, tid);
            chunk_compute<5>(hb, Wrz, Wn, kh, jl, bA, aR, aZ, aN);
            __syncthreads(); chunk_issue(hb, hsrc, 7, tid);
            chunk_compute<6>(hb, Wrz, Wn, kh, jl, bA, aR, aZ, aN);
            chunk_compute<7>(hb, Wrz, Wn, kh, jl, bA, aR, aZ, aN);

            // Cross-k-half reduction via smem (P sits in dead buf0 region:
            // 256 threads x 6 u64 = 12 KB < 16 KB; chunk7 data lives in buf1).
            u64* P = (u64*)hb;
            if (kh == 1) {
                u64* pp = P + (size_t)rm * 6;
                pp[0] = aR[0]; pp[1] = aR[1];
                pp[2] = aZ[0]; pp[3] = aZ[1];
                pp[4] = aN[0]; pp[5] = aN[1];
            }
            __syncthreads();

            if (kh == 0) {
                const u64* pp = P + (size_t)rm * 6;
                add2(aR[0], pp[0]); add2(aR[1], pp[1]);
                add2(aZ[0], pp[2]); add2(aZ[1], pp[3]);
                add2(aN[0], pp[4]); add2(aN[1], pp[5]);

                float R[4], Z[4], N[4];
#pragma unroll
                for (int p = 0; p < 2; p++) {
                    float2 r = up2(aR[p]), z = up2(aZ[p]), n = up2(aN[p]);
                    R[2*p] = r.x; R[2*p+1] = r.y;
                    Z[2*p] = z.x; Z[2*p+1] = z.y;
                    N[2*p] = n.x; N[2*p+1] = n.y;
                }

                if (grp == 1) {
                    float* q = g_gi1 + (size_t)((s - 1) & 1) * (G3H * 64);
                    float o[4];
#pragma unroll
                    for (int i = 0; i < 4; i++) o[i] = R[i] + br;
                    *(float4*)&q[(size_t)j * 64 + bA] = *(float4*)&o[0];
#pragma unroll
                    for (int i = 0; i < 4; i++) o[i] = Z[i] + bz;
                    *(float4*)&q[(size_t)(512 + j) * 64 + bA] = *(float4*)&o[0];
#pragma unroll
                    for (int i = 0; i < 4; i++) o[i] = N[i] + bn;
                    *(float4*)&q[(size_t)(1024 + j) * 64 + bA] = *(float4*)&o[0];
                } else {
                    float hn[4];
#pragma unroll
                    for (int i = 0; i < 4; i++) {
                        float r_ = sigmoidf_(GIR[i] + R[i] + br);
                        float z_ = sigmoidf_(GIZ[i] + Z[i] + bz);
                        float n_ = tanhf(GIN[i] + r_ * (N[i] + bn));
                        hn[i] = (1.f - z_) * n_ + z_ * hold[i];
                    }

                    const int tau = (grp == 2) ? s - 2 : s;
                    float* hdT = ((grp == 2) ? g_h1T : g_h0T) + (tau & 1) * (H_ * B_);
                    *(float4*)&hdT[j * 64 + bA] = *(float4*)&hn[0];

                    if (grp == 2) {
                        float* hq = g_h1sq + (size_t)tau * (H_ * B_);
                        *(float4*)&hq[j * 64 + bA] = *(float4*)&hn[0];
                    }
                    if (tau == S_ - 1) {
                        float* hd = hid + (grp == 2 ? B_ * H_ : 0);
#pragma unroll
                        for (int i = 0; i < 4; i++)
                            hd[(size_t)(bA + i) * H_ + j] = hn[i];
                    }
                }
            }
        }

        // ---- single-counter grid barrier: fire-and-forget red + acquire poll ----
        __syncthreads();
        if (tid == 0) {
            __threadfence();
            asm volatile("red.relaxed.gpu.global.add.u32 [%0], %1;"
                         :: "l"(&g_sync[0]), "r"(1u) : "memory");
            const unsigned tgt = (unsigned)(s + 1) * GR;
            unsigned v;
            do {
                asm volatile("ld.acquire.gpu.global.u32 %0, [%1];"
                             : "=r"(v) : "l"(&g_sync[0]));
            } while (v < tgt);
            __threadfence();
        }
        __syncthreads();
    }
}

// ---------------------------------------------------------------------------
// Launch
// ---------------------------------------------------------------------------
extern "C" void kernel_launch(void* const* d_in, const int* in_sizes, int n_in,
                              void* d_out, int out_size)
{
    const float* x    = (const float*)d_in[0];
    const float* Wih0 = (const float*)d_in[1];
    const float* Whh0 = (const float*)d_in[2];
    const float* bih0 = (const float*)d_in[3];
    const float* bhh0 = (const float*)d_in[4];
    const float* Wih1 = (const float*)d_in[5];
    const float* Whh1 = (const float*)d_in[6];
    const float* bih1 = (const float*)d_in[7];
    const float* bhh1 = (const float*)d_in[8];
    const float* Wfc  = (const float*)d_in[9];
    const float* bfc  = (const float*)d_in[10];

    float* out = (float*)d_out;                    // logits [B][S][O]
    float* hid = out + (size_t)B_ * S_ * O_;       // hidden [2][B][H]

    float *gi0, *h1sq, *h0T, *h1T;
    unsigned* sy;
    cudaGetSymbolAddress((void**)&gi0,  g_gi0);
    cudaGetSymbolAddress((void**)&h1sq, g_h1sq);
    cudaGetSymbolAddress((void**)&h0T,  g_h0T);
    cudaGetSymbolAddress((void**)&h1T,  g_h1T);
    cudaGetSymbolAddress((void**)&sy,   g_sync);

    cudaFuncSetAttribute(gru_fused, cudaFuncAttributeMaxDynamicSharedMemorySize,
                         FUS_SMEM_BYTES);

    const int M = B_ * S_;
    dim3 blk(256);
    dim3 gGI(G3H / 64, M / 128);   // 24 x 512
    dim3 gFC(O_ / 64, M / 128);    //  8 x 512

    // gi0 = x @ W_ih0^T + b_ih0   -> [t][row][b]
    sgemm_bias<0><<<gGI, blk>>>(x, Wih0, bih0, gi0, M, G3H, I_);

    cudaMemsetAsync(h0T, 0, (size_t)2 * H_ * B_ * sizeof(float));
    cudaMemsetAsync(h1T, 0, (size_t)2 * H_ * B_ * sizeof(float));
    cudaMemsetAsync(sy, 0, 32 * sizeof(unsigned));

    gru_fused<<<GR, RT, FUS_SMEM_BYTES>>>(gi0, Whh0, bhh0, Wih1, bih1,
                                          Whh1, bhh1, hid);

    // logits = hseq1 @ W_fc^T + b_fc   (A read from transposed [t][j][b])
    sgemm_bias<3><<<gFC, blk>>>(h1sq, Wfc, bfc, out, M, O_, H_);
}

// round 11
// speedup vs baseline: 1.1741x; 1.1741x over previous
#include <cuda_runtime.h>
#include <cstdint>
#include <math.h>

#define B_   64
#define S_   1024
#define I_   256
#define H_   512
#define O_   512
#define G3H  1536

#define GR    96     // 3 groups x 32 CTAs, all resident (1 CTA/SM via smem)
#define RT    256    // 8 warps -> 2 per SMSP
#define STEPS 1026

typedef unsigned long long u64;

// ---------------------------------------------------------------------------
// Device-global scratch
// ---------------------------------------------------------------------------
__device__ float    g_gi0  [(size_t)S_ * G3H * B_];   // gi0 [t][row][b]
__device__ float    g_gi1  [2 * G3H * B_];            // gi1 ring [slot][row][b]
__device__ float    g_h1sq [(size_t)S_ * H_ * B_];    // hseq1 transposed [t][j][b]
__device__ float    g_h0T  [2 * H_ * B_];             // h0 double buffer [slot][j][b]
__device__ float    g_h1T  [2 * H_ * B_];             // h1 double buffer [slot][j][b]
__device__ unsigned g_sync [512];                     // [g*32] grp ctr, [400] root, [416] release

// ---------------------------------------------------------------------------
// f32x2 + cp.async helpers
// ---------------------------------------------------------------------------
__device__ __forceinline__ u64 pk2(float x) {
    u64 r; asm("mov.b64 %0, {%1, %1};" : "=l"(r) : "r"(__float_as_uint(x))); return r;
}
__device__ __forceinline__ void fma2(u64& d, u64 a, u64 b) {
    asm("fma.rn.f32x2 %0, %1, %2, %0;" : "+l"(d) : "l"(a), "l"(b));
}
__device__ __forceinline__ float2 up2(u64 u) {
    unsigned lo, hi; asm("mov.b64 {%0, %1}, %2;" : "=r"(lo), "=r"(hi) : "l"(u));
    return make_float2(__uint_as_float(lo), __uint_as_float(hi));
}
__device__ __forceinline__ void cpa16(float* smem, const float* g) {
    unsigned s = (unsigned)__cvta_generic_to_shared(smem);
    asm volatile("cp.async.cg.shared.global [%0], [%1], 16;" :: "r"(s), "l"(g));
}
__device__ __forceinline__ float sigmoidf_(float x) { return 1.f / (1.f + expf(-x)); }

// ---------------------------------------------------------------------------
// SGEMM + bias. MODE 0: gi layout. MODE 3: logits layout. (unchanged)
// ---------------------------------------------------------------------------
template <int MODE>
__global__ void __launch_bounds__(256)
sgemm_bias(const float* __restrict__ A, const float* __restrict__ Bw,
           const float* __restrict__ bias, float* __restrict__ out,
           int M, int N, int K)
{
    __shared__ float As[16][132];
    __shared__ float Bs[16][68];

    const int tid = threadIdx.x;
    const int m0  = blockIdx.y * 128;
    const int n0  = blockIdx.x * 64;
    const int tx  = tid & 15;
    const int ty  = tid >> 4;

    const float* Bb = Bw + (size_t)n0 * K;

    u64 acc[4][4];
#pragma unroll
    for (int i = 0; i < 4; i++)
#pragma unroll
        for (int j = 0; j < 4; j++) acc[i][j] = 0ull;

    const int lr = tid >> 2;
    const int lk = (tid & 3) * 4;
    const int t0 = m0 >> 6;
    const int kk = tid >> 4, qq = tid & 15;

    for (int kt = 0; kt < K; kt += 16) {
        if (MODE == 0) {
            const float* Ab = A + (size_t)m0 * K;
#pragma unroll
            for (int p = 0; p < 2; p++) {
                float4 v = *(const float4*)&Ab[(size_t)(lr + p * 64) * K + kt + lk];
                As[lk + 0][lr + p * 64] = v.x;
                As[lk + 1][lr + p * 64] = v.y;
                As[lk + 2][lr + p * 64] = v.z;
                As[lk + 3][lr + p * 64] = v.w;
            }
        } else {
            float4 v0 = *(const float4*)&A[(((size_t)t0       * 512) + kt + kk) * 64 + qq * 4];
            float4 v1 = *(const float4*)&A[(((size_t)(t0 + 1) * 512) + kt + kk) * 64 + qq * 4];
            *(float4*)&As[kk][qq * 4]      = v0;
            *(float4*)&As[kk][64 + qq * 4] = v1;
        }
        {
            float4 v = *(const float4*)&Bb[(size_t)lr * K + kt + lk];
            Bs[lk + 0][lr] = v.x;
            Bs[lk + 1][lr] = v.y;
            Bs[lk + 2][lr] = v.z;
            Bs[lk + 3][lr] = v.w;
        }
        __syncthreads();

#pragma unroll
        for (int k = 0; k < 16; k++) {
            float4 bv = *(const float4*)&Bs[k][tx * 4];
            u64 bp0 = pk2(bv.x), bp1 = pk2(bv.y), bp2 = pk2(bv.z), bp3 = pk2(bv.w);
            ulonglong2 a01 = *(const ulonglong2*)&As[k][ty * 8];
            ulonglong2 a23 = *(const ulonglong2*)&As[k][ty * 8 + 4];
            u64 ap[4] = {a01.x, a01.y, a23.x, a23.y};
#pragma unroll
            for (int i = 0; i < 4; i++) {
                fma2(acc[i][0], ap[i], bp0);
                fma2(acc[i][1], ap[i], bp1);
                fma2(acc[i][2], ap[i], bp2);
                fma2(acc[i][3], ap[i], bp3);
            }
        }
        __syncthreads();
    }

    float accf[8][4];
#pragma unroll
    for (int i = 0; i < 4; i++)
#pragma unroll
        for (int j = 0; j < 4; j++) {
            float2 v = up2(acc[i][j]);
            accf[2 * i + 0][j] = v.x;
            accf[2 * i + 1][j] = v.y;
        }

    float bv[4];
    *(float4*)bv = *(const float4*)&bias[n0 + tx * 4];

#pragma unroll
    for (int i = 0; i < 8; i++) {
        int m = m0 + ty * 8 + i;
        if (MODE == 3) {
            int t = m >> 6, b = m & 63;
            float4 c;
            c.x = accf[i][0] + bv[0];
            c.y = accf[i][1] + bv[1];
            c.z = accf[i][2] + bv[2];
            c.w = accf[i][3] + bv[3];
            *(float4*)&out[((size_t)b * S_ + t) * O_ + n0 + tx * 4] = c;
        } else {
            int t = m & (S_ - 1), b = m >> 10;
#pragma unroll
            for (int j = 0; j < 4; j++)
                out[((size_t)t * G3H + n0 + tx * 4 + j) * B_ + b] = accf[i][j] + bv[j];
        }
    }
}

// ---------------------------------------------------------------------------
// Fused two-layer GRU wavefront. 96 CTAs = 3 groups x 32 (16 j each), RT=256.
//  G0: h0[s] = cell(h0[s-1], gi0[s]);  G1: gi1[s-1] = h0[s-1]@W_ih1^T + b;
//  G2: h1[s-2] = cell(h1[s-3], gi1[s-2]).
// FULL 128 KB h buffer in smem: all 8 cp.async groups issued up-front, only
// TWO wait+sync points per step (half-step granularity). No k-split, no
// reduce phase; thread = (jl, bs): 16 j x 16 b-groups of 4, 6 u64 accums.
// smem bytes: hs 131072 @0 | Wrz float2 65536 @131072 | Wn float 32768 @196608
// ---------------------------------------------------------------------------
#define FUS_SMEM_BYTES 229376

__device__ __forceinline__ void compute_half(const float* __restrict__ hs,
                                             const float2* __restrict__ Wrz,
                                             const float* __restrict__ Wn,
                                             int jl, int bA, int k0,
                                             u64* aR, u64* aZ, u64* aN)
{
#pragma unroll 8
    for (int k = k0; k < k0 + 256; k++) {
        float2 w2 = Wrz[k * 16 + jl];
        float  wf = Wn [k * 16 + jl];
        u64 wr = pk2(w2.x), wz = pk2(w2.y), wn = pk2(wf);
        ulonglong2 h = *(const ulonglong2*)&hs[k * 64 + bA];
        fma2(aR[0], h.x, wr); fma2(aR[1], h.y, wr);
        fma2(aZ[0], h.x, wz); fma2(aZ[1], h.y, wz);
        fma2(aN[0], h.x, wn); fma2(aN[1], h.y, wn);
    }
}

__global__ void __launch_bounds__(RT, 1)
gru_fused(const float* __restrict__ gi0,
          const float* __restrict__ Whh0, const float* __restrict__ bhh0,
          const float* __restrict__ Wih1, const float* __restrict__ bih1,
          const float* __restrict__ Whh1, const float* __restrict__ bhh1,
          float* __restrict__ hid)    // [2][B][H] tail of d_out
{
    extern __shared__ float sm[];
    float*  hs  = sm;                            // 131072 B (full h state)
    float2* Wrz = (float2*)(sm + 32768);         // 65536 B
    float*  Wn  = sm + 49152;                    // 32768 B

    const int tid   = threadIdx.x;
    const int cta   = blockIdx.x;
    const int grp   = cta >> 5;
    const int lc    = cta & 31;
    const int jbase = lc * 16;

    const float* Wsrc = (grp == 0) ? Whh0 : (grp == 1) ? Wih1 : Whh1;

    // Weight slice preload: 16 j x 512 k x 3 gates, k-major.
    for (int i = tid; i < 16 * 512; i += RT) {
        int k = i & 511, jj = i >> 9;
        int j = jbase + jj;
        float wr = Wsrc[(size_t)j          * 512 + k];
        float wz = Wsrc[(size_t)(512 + j)  * 512 + k];
        float wn = Wsrc[(size_t)(1024 + j) * 512 + k];
        Wrz[k * 16 + jj] = make_float2(wr, wz);
        Wn [k * 16 + jj] = wn;
    }

    const int jl = tid >> 4;       // 0..15
    const int bs = tid & 15;       // 0..15
    const int bA = bs * 4;         // 4 batch per thread
    const int j  = jbase + jl;

    float br = 0.f, bz = 0.f, bn = 0.f;
    if (grp == 0) { br = bhh0[j]; bz = bhh0[512 + j]; bn = bhh0[1024 + j]; }
    if (grp == 1) { br = bih1[j]; bz = bih1[512 + j]; bn = bih1[1024 + j]; }
    if (grp == 2) { br = bhh1[j]; bz = bhh1[512 + j]; bn = bhh1[1024 + j]; }

    __syncthreads();

    for (int s = 0; s < STEPS; s++) {
        const bool active = (grp == 0) ? (s < 1024)
                          : (grp == 1) ? (s >= 1 && s < 1025)
                                       : (s >= 2);
        if (active) {
            const float* hsrc = ((grp == 2) ? g_h1T : g_h0T)
                              + (((grp == 2 ? s - 2 : s) + 1) & 1) * (H_ * B_);

            // Issue ALL 8 chunk groups (16 KB each) covering the full h state.
#pragma unroll
            for (int c = 0; c < 8; c++) {
                const float* s4 = hsrc + c * 4096;
                float*       d4 = hs   + c * 4096;
#pragma unroll
                for (int u = 0; u < 4; u++)
                    cpa16(d4 + (tid + u * RT) * 4, s4 + (tid + u * RT) * 4);
                asm volatile("cp.async.commit_group;");
            }

            // Prefetch gi into registers (lands under the mainloop)
            float GIR[4], GIZ[4], GIN[4];
            if (grp != 1) {
                const float* p = (grp == 0)
                    ? gi0   + (size_t)s * (G3H * 64)
                    : g_gi1 + (size_t)(s & 1) * (G3H * 64);
                *(float4*)&GIR[0] = *(const float4*)&p[(size_t)j          * 64 + bA];
                *(float4*)&GIZ[0] = *(const float4*)&p[(size_t)(512 + j)  * 64 + bA];
                *(float4*)&GIN[0] = *(const float4*)&p[(size_t)(1024 + j) * 64 + bA];
            }

            u64 aR[2] = {0,0}, aZ[2] = {0,0}, aN[2] = {0,0};

            // First half: chunks 0..3 arrived (4 groups still pending)
            asm volatile("cp.async.wait_group 4;");
            __syncthreads();
            compute_half(hs, Wrz, Wn, jl, bA, 0,   aR, aZ, aN);

            // Second half: everything arrived
            asm volatile("cp.async.wait_group 0;");
            __syncthreads();
            compute_half(hs, Wrz, Wn, jl, bA, 256, aR, aZ, aN);

            float R[4], Z[4], N[4];
#pragma unroll
            for (int p = 0; p < 2; p++) {
                float2 r = up2(aR[p]), z = up2(aZ[p]), n = up2(aN[p]);
                R[2*p] = r.x; R[2*p+1] = r.y;
                Z[2*p] = z.x; Z[2*p+1] = z.y;
                N[2*p] = n.x; N[2*p+1] = n.y;
            }

            if (grp == 1) {
                float* q = g_gi1 + (size_t)((s - 1) & 1) * (G3H * 64);
                float o[4];
#pragma unroll
                for (int i = 0; i < 4; i++) o[i] = R[i] + br;
                *(float4*)&q[(size_t)j * 64 + bA] = *(float4*)&o[0];
#pragma unroll
                for (int i = 0; i < 4; i++) o[i] = Z[i] + bz;
                *(float4*)&q[(size_t)(512 + j) * 64 + bA] = *(float4*)&o[0];
#pragma unroll
                for (int i = 0; i < 4; i++) o[i] = N[i] + bn;
                *(float4*)&q[(size_t)(1024 + j) * 64 + bA] = *(float4*)&o[0];
            } else {
                // h_old free from the resident smem h buffer
                float hold[4];
                *(float4*)&hold[0] = *(const float4*)&hs[j * 64 + bA];

                float hn[4];
#pragma unroll
                for (int i = 0; i < 4; i++) {
                    float r_ = sigmoidf_(GIR[i] + R[i] + br);
                    float z_ = sigmoidf_(GIZ[i] + Z[i] + bz);
                    float n_ = tanhf(GIN[i] + r_ * (N[i] + bn));
                    hn[i] = (1.f - z_) * n_ + z_ * hold[i];
                }

                const int tau = (grp == 2) ? s - 2 : s;
                float* hdT = ((grp == 2) ? g_h1T : g_h0T) + (tau & 1) * (H_ * B_);
                *(float4*)&hdT[j * 64 + bA] = *(float4*)&hn[0];

                if (grp == 2) {
                    float* hq = g_h1sq + (size_t)tau * (H_ * B_);
                    *(float4*)&hq[j * 64 + bA] = *(float4*)&hn[0];
                }
                if (tau == S_ - 1) {
                    float* hd = hid + (grp == 2 ? B_ * H_ : 0);
#pragma unroll
                    for (int i = 0; i < 4; i++)
                        hd[(size_t)(bA + i) * H_ + j] = hn[i];
                }
            }
        }

        // ---- two-level grid barrier (R8 known-good) ----
        __syncthreads();
        if (tid == 0) {
            __threadfence();
            unsigned go = atomicAdd(&g_sync[(cta >> 3) * 32], 1u);
            if (go == (unsigned)(s + 1) * 8 - 1) {
                unsigned ro = atomicAdd(&g_sync[400], 1u);
                if (ro == (unsigned)(s + 1) * 12 - 1) {
                    __threadfence();
                    *((volatile unsigned*)&g_sync[416]) = (unsigned)(s + 1);
                }
            }
            while (*((volatile unsigned*)&g_sync[416]) < (unsigned)(s + 1)) { }
            __threadfence();
        }
        __syncthreads();
    }
}

// ---------------------------------------------------------------------------
// Launch
// ---------------------------------------------------------------------------
extern "C" void kernel_launch(void* const* d_in, const int* in_sizes, int n_in,
                              void* d_out, int out_size)
{
    const float* x    = (const float*)d_in[0];
    const float* Wih0 = (const float*)d_in[1];
    const float* Whh0 = (const float*)d_in[2];
    const float* bih0 = (const float*)d_in[3];
    const float* bhh0 = (const float*)d_in[4];
    const float* Wih1 = (const float*)d_in[5];
    const float* Whh1 = (const float*)d_in[6];
    const float* bih1 = (const float*)d_in[7];
    const float* bhh1 = (const float*)d_in[8];
    const float* Wfc  = (const float*)d_in[9];
    const float* bfc  = (const float*)d_in[10];

    float* out = (float*)d_out;                    // logits [B][S][O]
    float* hid = out + (size_t)B_ * S_ * O_;       // hidden [2][B][H]

    float *gi0, *h1sq, *h0T, *h1T;
    unsigned* sy;
    cudaGetSymbolAddress((void**)&gi0,  g_gi0);
    cudaGetSymbolAddress((void**)&h1sq, g_h1sq);
    cudaGetSymbolAddress((void**)&h0T,  g_h0T);
    cudaGetSymbolAddress((void**)&h1T,  g_h1T);
    cudaGetSymbolAddress((void**)&sy,   g_sync);

    cudaFuncSetAttribute(gru_fused, cudaFuncAttributeMaxDynamicSharedMemorySize,
                         FUS_SMEM_BYTES);

    const int M = B_ * S_;
    dim3 blk(256);
    dim3 gGI(G3H / 64, M / 128);   // 24 x 512
    dim3 gFC(O_ / 64, M / 128);    //  8 x 512

    // gi0 = x @ W_ih0^T + b_ih0   -> [t][row][b]
    sgemm_bias<0><<<gGI, blk>>>(x, Wih0, bih0, gi0, M, G3H, I_);

    cudaMemsetAsync(h0T, 0, (size_t)2 * H_ * B_ * sizeof(float));
    cudaMemsetAsync(h1T, 0, (size_t)2 * H_ * B_ * sizeof(float));
    cudaMemsetAsync(sy, 0, 512 * sizeof(unsigned));

    gru_fused<<<GR, RT, FUS_SMEM_BYTES>>>(gi0, Whh0, bhh0, Wih1, bih1,
                                          Whh1, bhh1, hid);

    // logits = hseq1 @ W_fc^T + b_fc   (A read from transposed [t][j][b])
    sgemm_bias<3><<<gFC, blk>>>(h1sq, Wfc, bfc, out, M, O_, H_);
}

// round 12
// speedup vs baseline: 1.2630x; 1.0758x over previous
#include <cuda_runtime.h>
#include <cstdint>
#include <math.h>

#define B_   64
#define S_   1024
#define I_   256
#define H_   512
#define O_   512
#define G3H  1536

#define GR    96     // 3 groups x 32 CTAs, all resident (1 CTA/SM via smem)
#define RT    256    // 8 warps -> 2 per SMSP
#define STEPS 1026

typedef unsigned long long u64;

// ---------------------------------------------------------------------------
// Device-global scratch
// ---------------------------------------------------------------------------
__device__ float    g_gi0  [(size_t)S_ * G3H * B_];   // gi0 [t][row][b]
__device__ float    g_gi1  [2 * G3H * B_];            // gi1 ring [slot][row][b]
__device__ float    g_h1sq [(size_t)S_ * H_ * B_];    // hseq1 transposed [t][j][b]
__device__ float    g_h0T  [2 * H_ * B_];             // h0 double buffer [slot][j][b]
__device__ float    g_h1T  [2 * H_ * B_];             // h1 double buffer [slot][j][b]
__device__ unsigned g_sync [512];                     // [g*32] grp ctr, [400] root, [416] release

// ---------------------------------------------------------------------------
// f32x2 + cp.async helpers
// ---------------------------------------------------------------------------
__device__ __forceinline__ u64 pk2(float x) {
    u64 r; asm("mov.b64 %0, {%1, %1};" : "=l"(r) : "r"(__float_as_uint(x))); return r;
}
__device__ __forceinline__ void fma2(u64& d, u64 a, u64 b) {
    asm("fma.rn.f32x2 %0, %1, %2, %0;" : "+l"(d) : "l"(a), "l"(b));
}
__device__ __forceinline__ float2 up2(u64 u) {
    unsigned lo, hi; asm("mov.b64 {%0, %1}, %2;" : "=r"(lo), "=r"(hi) : "l"(u));
    return make_float2(__uint_as_float(lo), __uint_as_float(hi));
}
__device__ __forceinline__ void cpa16(float* smem, const float* g) {
    unsigned s = (unsigned)__cvta_generic_to_shared(smem);
    asm volatile("cp.async.cg.shared.global [%0], [%1], 16;" :: "r"(s), "l"(g));
}
__device__ __forceinline__ float sigmoidf_(float x) { return 1.f / (1.f + expf(-x)); }

// ---------------------------------------------------------------------------
// SGEMM + bias.
// MODE 0: A = x [B][S][I], M ordered m = t*64 + b  -> out gi[t][n][b],
//         epilogue stores float4 ALONG b (f32x2 pair axis == b) -> coalesced.
// MODE 3: A = h1sq [t][k][b] (rows m = t*64+b)     -> out[b][t][n].
// BM=128 BN=64 BK=16, 256 thr, f32x2 mainloop.
// ---------------------------------------------------------------------------
template <int MODE>
__global__ void __launch_bounds__(256)
sgemm_bias(const float* __restrict__ A, const float* __restrict__ Bw,
           const float* __restrict__ bias, float* __restrict__ out,
           int M, int N, int K)
{
    __shared__ float As[16][132];
    __shared__ float Bs[16][68];

    const int tid = threadIdx.x;
    const int m0  = blockIdx.y * 128;
    const int n0  = blockIdx.x * 64;
    const int tx  = tid & 15;
    const int ty  = tid >> 4;

    const float* Bb = Bw + (size_t)n0 * K;

    u64 acc[4][4];
#pragma unroll
    for (int i = 0; i < 4; i++)
#pragma unroll
        for (int j = 0; j < 4; j++) acc[i][j] = 0ull;

    const int lr = tid >> 2;
    const int lk = (tid & 3) * 4;
    const int t0 = m0 >> 6;
    const int kk = tid >> 4, qq = tid & 15;

    for (int kt = 0; kt < K; kt += 16) {
        if (MODE == 0) {
            // row r of block: t = t0 + (r>>6), b = r&63; x[b][t][k]
#pragma unroll
            for (int p = 0; p < 2; p++) {
                const int r = lr + p * 64;
                float4 v = *(const float4*)&A[((size_t)(r & 63) * S_ + t0 + (r >> 6)) * I_ + kt + lk];
                As[lk + 0][r] = v.x;
                As[lk + 1][r] = v.y;
                As[lk + 2][r] = v.z;
                As[lk + 3][r] = v.w;
            }
        } else {
            float4 v0 = *(const float4*)&A[(((size_t)t0       * 512) + kt + kk) * 64 + qq * 4];
            float4 v1 = *(const float4*)&A[(((size_t)(t0 + 1) * 512) + kt + kk) * 64 + qq * 4];
            *(float4*)&As[kk][qq * 4]      = v0;
            *(float4*)&As[kk][64 + qq * 4] = v1;
        }
        {
            float4 v = *(const float4*)&Bb[(size_t)lr * K + kt + lk];
            Bs[lk + 0][lr] = v.x;
            Bs[lk + 1][lr] = v.y;
            Bs[lk + 2][lr] = v.z;
            Bs[lk + 3][lr] = v.w;
        }
        __syncthreads();

#pragma unroll
        for (int k = 0; k < 16; k++) {
            float4 bv = *(const float4*)&Bs[k][tx * 4];
            u64 bp0 = pk2(bv.x), bp1 = pk2(bv.y), bp2 = pk2(bv.z), bp3 = pk2(bv.w);
            ulonglong2 a01 = *(const ulonglong2*)&As[k][ty * 8];
            ulonglong2 a23 = *(const ulonglong2*)&As[k][ty * 8 + 4];
            u64 ap[4] = {a01.x, a01.y, a23.x, a23.y};
#pragma unroll
            for (int i = 0; i < 4; i++) {
                fma2(acc[i][0], ap[i], bp0);
                fma2(acc[i][1], ap[i], bp1);
                fma2(acc[i][2], ap[i], bp2);
                fma2(acc[i][3], ap[i], bp3);
            }
        }
        __syncthreads();
    }

    float bv[4];
    *(float4*)bv = *(const float4*)&bias[n0 + tx * 4];

    if (MODE == 0) {
        // Thread owns 8 consecutive b (pairs along M==b) at one t.
        const int t  = t0 + (ty >> 3);
        const int b0 = (ty & 7) * 8;
#pragma unroll
        for (int j = 0; j < 4; j++) {
            const int n = n0 + tx * 4 + j;
            float2 p0 = up2(acc[0][j]), p1 = up2(acc[1][j]);
            float2 p2 = up2(acc[2][j]), p3 = up2(acc[3][j]);
            float4 w0, w1;
            w0.x = p0.x + bv[j]; w0.y = p0.y + bv[j];
            w0.z = p1.x + bv[j]; w0.w = p1.y + bv[j];
            w1.x = p2.x + bv[j]; w1.y = p2.y + bv[j];
            w1.z = p3.x + bv[j]; w1.w = p3.y + bv[j];
            float* q = out + ((size_t)t * G3H + n) * B_ + b0;
            *(float4*)&q[0] = w0;
            *(float4*)&q[4] = w1;
        }
    } else {
        float accf[8][4];
#pragma unroll
        for (int i = 0; i < 4; i++)
#pragma unroll
            for (int j = 0; j < 4; j++) {
                float2 v = up2(acc[i][j]);
                accf[2 * i + 0][j] = v.x;
                accf[2 * i + 1][j] = v.y;
            }
#pragma unroll
        for (int i = 0; i < 8; i++) {
            int m = m0 + ty * 8 + i;
            int t = m >> 6, b = m & 63;
            float4 c;
            c.x = accf[i][0] + bv[0];
            c.y = accf[i][1] + bv[1];
            c.z = accf[i][2] + bv[2];
            c.w = accf[i][3] + bv[3];
            *(float4*)&out[((size_t)b * S_ + t) * O_ + n0 + tx * 4] = c;
        }
    }
}

// ---------------------------------------------------------------------------
// Fused two-layer GRU wavefront (UNCHANGED from R10 best-known config).
// 96 CTAs = 3 groups x 32 (16 j each), RT=256.
//  G0: h0[s] = cell(h0[s-1], gi0[s]);  G1: gi1[s-1] = h0[s-1]@W_ih1^T + b;
//  G2: h1[s-2] = cell(h1[s-3], gi1[s-2]).
// FULL 128 KB h buffer in smem; all 8 cp.async groups issued up-front, two
// wait+sync points per step. Thread = (jl, bs): 16 j x 16 b-groups of 4.
// smem bytes: hs 131072 @0 | Wrz float2 65536 @131072 | Wn float 32768 @196608
// ---------------------------------------------------------------------------
#define FUS_SMEM_BYTES 229376

__device__ __forceinline__ void compute_half(const float* __restrict__ hs,
                                             const float2* __restrict__ Wrz,
                                             const float* __restrict__ Wn,
                                             int jl, int bA, int k0,
                                             u64* aR, u64* aZ, u64* aN)
{
#pragma unroll 8
    for (int k = k0; k < k0 + 256; k++) {
        float2 w2 = Wrz[k * 16 + jl];
        float  wf = Wn [k * 16 + jl];
        u64 wr = pk2(w2.x), wz = pk2(w2.y), wn = pk2(wf);
        ulonglong2 h = *(const ulonglong2*)&hs[k * 64 + bA];
        fma2(aR[0], h.x, wr); fma2(aR[1], h.y, wr);
        fma2(aZ[0], h.x, wz); fma2(aZ[1], h.y, wz);
        fma2(aN[0], h.x, wn); fma2(aN[1], h.y, wn);
    }
}

__global__ void __launch_bounds__(RT, 1)
gru_fused(const float* __restrict__ gi0,
          const float* __restrict__ Whh0, const float* __restrict__ bhh0,
          const float* __restrict__ Wih1, const float* __restrict__ bih1,
          const float* __restrict__ Whh1, const float* __restrict__ bhh1,
          float* __restrict__ hid)    // [2][B][H] tail of d_out
{
    extern __shared__ float sm[];
    float*  hs  = sm;                            // 131072 B (full h state)
    float2* Wrz = (float2*)(sm + 32768);         // 65536 B
    float*  Wn  = sm + 49152;                    // 32768 B

    const int tid   = threadIdx.x;
    const int cta   = blockIdx.x;
    const int grp   = cta >> 5;
    const int lc    = cta & 31;
    const int jbase = lc * 16;

    const float* Wsrc = (grp == 0) ? Whh0 : (grp == 1) ? Wih1 : Whh1;

    // Weight slice preload: 16 j x 512 k x 3 gates, k-major.
    for (int i = tid; i < 16 * 512; i += RT) {
        int k = i & 511, jj = i >> 9;
        int j = jbase + jj;
        float wr = Wsrc[(size_t)j          * 512 + k];
        float wz = Wsrc[(size_t)(512 + j)  * 512 + k];
        float wn = Wsrc[(size_t)(1024 + j) * 512 + k];
        Wrz[k * 16 + jj] = make_float2(wr, wz);
        Wn [k * 16 + jj] = wn;
    }

    const int jl = tid >> 4;       // 0..15
    const int bs = tid & 15;       // 0..15
    const int bA = bs * 4;         // 4 batch per thread
    const int j  = jbase + jl;

    float br = 0.f, bz = 0.f, bn = 0.f;
    if (grp == 0) { br = bhh0[j]; bz = bhh0[512 + j]; bn = bhh0[1024 + j]; }
    if (grp == 1) { br = bih1[j]; bz = bih1[512 + j]; bn = bih1[1024 + j]; }
    if (grp == 2) { br = bhh1[j]; bz = bhh1[512 + j]; bn = bhh1[1024 + j]; }

    __syncthreads();

    for (int s = 0; s < STEPS; s++) {
        const bool active = (grp == 0) ? (s < 1024)
                          : (grp == 1) ? (s >= 1 && s < 1025)
                                       : (s >= 2);
        if (active) {
            const float* hsrc = ((grp == 2) ? g_h1T : g_h0T)
                              + (((grp == 2 ? s - 2 : s) + 1) & 1) * (H_ * B_);

            // Issue ALL 8 chunk groups (16 KB each) covering the full h state.
#pragma unroll
            for (int c = 0; c < 8; c++) {
                const float* s4 = hsrc + c * 4096;
                float*       d4 = hs   + c * 4096;
#pragma unroll
                for (int u = 0; u < 4; u++)
                    cpa16(d4 + (tid + u * RT) * 4, s4 + (tid + u * RT) * 4);
                asm volatile("cp.async.commit_group;");
            }

            // Prefetch gi into registers (lands under the mainloop)
            float GIR[4], GIZ[4], GIN[4];
            if (grp != 1) {
                const float* p = (grp == 0)
                    ? gi0   + (size_t)s * (G3H * 64)
                    : g_gi1 + (size_t)(s & 1) * (G3H * 64);
                *(float4*)&GIR[0] = *(const float4*)&p[(size_t)j          * 64 + bA];
                *(float4*)&GIZ[0] = *(const float4*)&p[(size_t)(512 + j)  * 64 + bA];
                *(float4*)&GIN[0] = *(const float4*)&p[(size_t)(1024 + j) * 64 + bA];
            }

            u64 aR[2] = {0,0}, aZ[2] = {0,0}, aN[2] = {0,0};

            // First half: chunks 0..3 arrived (4 groups still pending)
            asm volatile("cp.async.wait_group 4;");
            __syncthreads();
            compute_half(hs, Wrz, Wn, jl, bA, 0,   aR, aZ, aN);

            // Second half: everything arrived
            asm volatile("cp.async.wait_group 0;");
            __syncthreads();
            compute_half(hs, Wrz, Wn, jl, bA, 256, aR, aZ, aN);

            float R[4], Z[4], N[4];
#pragma unroll
            for (int p = 0; p < 2; p++) {
                float2 r = up2(aR[p]), z = up2(aZ[p]), n = up2(aN[p]);
                R[2*p] = r.x; R[2*p+1] = r.y;
                Z[2*p] = z.x; Z[2*p+1] = z.y;
                N[2*p] = n.x; N[2*p+1] = n.y;
            }

            if (grp == 1) {
                float* q = g_gi1 + (size_t)((s - 1) & 1) * (G3H * 64);
                float o[4];
#pragma unroll
                for (int i = 0; i < 4; i++) o[i] = R[i] + br;
                *(float4*)&q[(size_t)j * 64 + bA] = *(float4*)&o[0];
#pragma unroll
                for (int i = 0; i < 4; i++) o[i] = Z[i] + bz;
                *(float4*)&q[(size_t)(512 + j) * 64 + bA] = *(float4*)&o[0];
#pragma unroll
                for (int i = 0; i < 4; i++) o[i] = N[i] + bn;
                *(float4*)&q[(size_t)(1024 + j) * 64 + bA] = *(float4*)&o[0];
            } else {
                // h_old free from the resident smem h buffer
                float hold[4];
                *(float4*)&hold[0] = *(const float4*)&hs[j * 64 + bA];

                float hn[4];
#pragma unroll
                for (int i = 0; i < 4; i++) {
                    float r_ = sigmoidf_(GIR[i] + R[i] + br);
                    float z_ = sigmoidf_(GIZ[i] + Z[i] + bz);
                    float n_ = tanhf(GIN[i] + r_ * (N[i] + bn));
                    hn[i] = (1.f - z_) * n_ + z_ * hold[i];
                }

                const int tau = (grp == 2) ? s - 2 : s;
                float* hdT = ((grp == 2) ? g_h1T : g_h0T) + (tau & 1) * (H_ * B_);
                *(float4*)&hdT[j * 64 + bA] = *(float4*)&hn[0];

                if (grp == 2) {
                    float* hq = g_h1sq + (size_t)tau * (H_ * B_);
                    *(float4*)&hq[j * 64 + bA] = *(float4*)&hn[0];
                }
                if (tau == S_ - 1) {
                    float* hd = hid + (grp == 2 ? B_ * H_ : 0);
#pragma unroll
                    for (int i = 0; i < 4; i++)
                        hd[(size_t)(bA + i) * H_ + j] = hn[i];
                }
            }
        }

        // ---- two-level grid barrier ----
        __syncthreads();
        if (tid == 0) {
            __threadfence();
            unsigned go = atomicAdd(&g_sync[(cta >> 3) * 32], 1u);
            if (go == (unsigned)(s + 1) * 8 - 1) {
                unsigned ro = atomicAdd(&g_sync[400], 1u);
                if (ro == (unsigned)(s + 1) * 12 - 1) {
                    __threadfence();
                    *((volatile unsigned*)&g_sync[416]) = (unsigned)(s + 1);
                }
            }
            while (*((volatile unsigned*)&g_sync[416]) < (unsigned)(s + 1)) { }
            __threadfence();
        }
        __syncthreads();
    }
}

// ---------------------------------------------------------------------------
// Launch
// ---------------------------------------------------------------------------
extern "C" void kernel_launch(void* const* d_in, const int* in_sizes, int n_in,
                              void* d_out, int out_size)
{
    const float* x    = (const float*)d_in[0];
    const float* Wih0 = (const float*)d_in[1];
    const float* Whh0 = (const float*)d_in[2];
    const float* bih0 = (const float*)d_in[3];
    const float* bhh0 = (const float*)d_in[4];
    const float* Wih1 = (const float*)d_in[5];
    const float* Whh1 = (const float*)d_in[6];
    const float* bih1 = (const float*)d_in[7];
    const float* bhh1 = (const float*)d_in[8];
    const float* Wfc  = (const float*)d_in[9];
    const float* bfc  = (const float*)d_in[10];

    float* out = (float*)d_out;                    // logits [B][S][O]
    float* hid = out + (size_t)B_ * S_ * O_;       // hidden [2][B][H]

    float *gi0, *h1sq, *h0T, *h1T;
    unsigned* sy;
    cudaGetSymbolAddress((void**)&gi0,  g_gi0);
    cudaGetSymbolAddress((void**)&h1sq, g_h1sq);
    cudaGetSymbolAddress((void**)&h0T,  g_h0T);
    cudaGetSymbolAddress((void**)&h1T,  g_h1T);
    cudaGetSymbolAddress((void**)&sy,   g_sync);

    cudaFuncSetAttribute(gru_fused, cudaFuncAttributeMaxDynamicSharedMemorySize,
                         FUS_SMEM_BYTES);

    const int M = B_ * S_;
    dim3 blk(256);
    dim3 gGI(G3H / 64, M / 128);   // 24 x 512
    dim3 gFC(O_ / 64, M / 128);    //  8 x 512

    // gi0 = x @ W_ih0^T + b_ih0   -> [t][row][b]  (coalesced b-axis stores)
    sgemm_bias<0><<<gGI, blk>>>(x, Wih0, bih0, gi0, M, G3H, I_);

    cudaMemsetAsync(h0T, 0, (size_t)2 * H_ * B_ * sizeof(float));
    cudaMemsetAsync(h1T, 0, (size_t)2 * H_ * B_ * sizeof(float));
    cudaMemsetAsync(sy, 0, 512 * sizeof(unsigned));

    gru_fused<<<GR, RT, FUS_SMEM_BYTES>>>(gi0, Whh0, bhh0, Wih1, bih1,
                                          Whh1, bhh1, hid);

    // logits = hseq1 @ W_fc^T + b_fc   (A read from transposed [t][j][b])
    sgemm_bias<3><<<gFC, blk>>>(h1sq, Wfc, bfc, out, M, O_, H_);
}